// round 2
// baseline (speedup 1.0000x reference)
#include <cuda_runtime.h>
#include <cuda_bf16.h>

// Scratch (device globals — no allocation allowed)
__device__ float g_sub[256];
__device__ float g_gia[768];   // gi for seed GRU (x = encoder_output)
__device__ float g_gha[768];   // gh for seed GRU (h = sub)
__device__ float g_r0[256];
__device__ float g_gi2[768];   // gi for edge GRU (x = r0, same for all edges)
__device__ float g_obj[1024 * 256];  // per-relation final output table (R <= 1024)

__device__ __forceinline__ float sigmoidf(float x) {
    return 1.0f / (1.0f + __expf(-x));
}

// K1: sub[d] = tanh(sample_mask . sub_W[d,:] + sub_b[d])   (1 block, 256 thr)
__global__ void k_sub(const float* __restrict__ mask, const float* __restrict__ sub_W,
                      const float* __restrict__ sub_b) {
    int d = threadIdx.x;
    float acc = sub_b[d];
    const float* w = sub_W + d * 256;
#pragma unroll 8
    for (int k = 0; k < 256; k++) acc = fmaf(mask[k], w[k], acc);
    g_sub[d] = tanhf(acc);
}

// K2: gia[j] = enc . W_ih[j,:] + b_ih[j];  gha[j] = sub . W_hh[j,:] + b_hh[j]
// grid = 3 blocks x 256
__global__ void k_gates_seed(const float* __restrict__ enc,
                             const float* __restrict__ W_ih, const float* __restrict__ W_hh,
                             const float* __restrict__ b_ih, const float* __restrict__ b_hh) {
    int j = blockIdx.x * 256 + threadIdx.x;
    float ga = b_ih[j];
    float gb = b_hh[j];
    const float* wi = W_ih + (size_t)j * 256;
    const float* wh = W_hh + (size_t)j * 256;
#pragma unroll 8
    for (int k = 0; k < 256; k++) {
        ga = fmaf(enc[k],  wi[k], ga);
        gb = fmaf(g_sub[k], wh[k], gb);
    }
    g_gia[j] = ga;
    g_gha[j] = gb;
}

// K3: r0[d] from gates   (1 block, 256 thr)
__global__ void k_r0() {
    int d = threadIdx.x;
    float r = sigmoidf(g_gia[d]       + g_gha[d]);
    float z = sigmoidf(g_gia[256 + d] + g_gha[256 + d]);
    float n = tanhf   (g_gia[512 + d] + r * g_gha[512 + d]);
    g_r0[d] = (1.0f - z) * n + z * g_sub[d];
}

// K4: gi2[j] = r0 . W_ih[j,:] + b_ih[j]   (3 blocks x 256)
__global__ void k_gi2(const float* __restrict__ W_ih, const float* __restrict__ b_ih) {
    int j = blockIdx.x * 256 + threadIdx.x;
    float acc = b_ih[j];
    const float* w = W_ih + (size_t)j * 256;
#pragma unroll 8
    for (int k = 0; k < 256; k++) acc = fmaf(g_r0[k], w[k], acc);
    g_gi2[j] = acc;
}

// K5: per-relation table. Each block handles RT=8 relations.
//   gh = rel_emb @ W_hh.T + b_hh ; gates with gi2 ; rj ; obj = tanh(rj @ obj_W.T + obj_b)
#define RT 8
__global__ void k_reltable(const float* __restrict__ rel_table,
                           const float* __restrict__ W_hh, const float* __restrict__ b_hh,
                           const float* __restrict__ obj_W, const float* __restrict__ obj_b,
                           int R) {
    __shared__ float srel[RT][256];
    int d = threadIdx.x;
    int rbase = blockIdx.x * RT;

    // load RT relation embeddings into smem
#pragma unroll
    for (int ri = 0; ri < RT; ri++) {
        int r = rbase + ri;
        srel[ri][d] = (r < R) ? rel_table[(size_t)r * 256 + d] : 0.0f;
    }
    __syncthreads();

    // phase 1: hidden-side gate GEMV, 3 gates x RT relations per thread
    float ar[RT], az[RT], an[RT];
    float br = b_hh[d], bz = b_hh[256 + d], bn = b_hh[512 + d];
#pragma unroll
    for (int ri = 0; ri < RT; ri++) { ar[ri] = br; az[ri] = bz; an[ri] = bn; }

    const float* wr = W_hh + (size_t)d * 256;
    const float* wz = W_hh + (size_t)(256 + d) * 256;
    const float* wn = W_hh + (size_t)(512 + d) * 256;
#pragma unroll 4
    for (int k = 0; k < 256; k++) {
        float vr = wr[k], vz = wz[k], vn = wn[k];
#pragma unroll
        for (int ri = 0; ri < RT; ri++) {
            float h = srel[ri][k];
            ar[ri] = fmaf(vr, h, ar[ri]);
            az[ri] = fmaf(vz, h, az[ri]);
            an[ri] = fmaf(vn, h, an[ri]);
        }
    }

    // gates -> rj (register), then swap into smem
    float gr = g_gi2[d], gz = g_gi2[256 + d], gn = g_gi2[512 + d];
    float rj[RT];
#pragma unroll
    for (int ri = 0; ri < RT; ri++) {
        float r = sigmoidf(gr + ar[ri]);
        float z = sigmoidf(gz + az[ri]);
        float n = tanhf(gn + r * an[ri]);
        rj[ri] = (1.0f - z) * n + z * srel[ri][d];
    }
    __syncthreads();
#pragma unroll
    for (int ri = 0; ri < RT; ri++) srel[ri][d] = rj[ri];
    __syncthreads();

    // phase 2: obj = tanh(rj @ obj_W.T + obj_b)
    float ao[RT];
    float bo = obj_b[d];
#pragma unroll
    for (int ri = 0; ri < RT; ri++) ao[ri] = bo;
    const float* wo = obj_W + (size_t)d * 256;
#pragma unroll 4
    for (int k = 0; k < 256; k++) {
        float v = wo[k];
#pragma unroll
        for (int ri = 0; ri < RT; ri++) ao[ri] = fmaf(v, srel[ri][k], ao[ri]);
    }
#pragma unroll
    for (int ri = 0; ri < RT; ri++) {
        int r = rbase + ri;
        if (r < R) g_obj[(size_t)r * 256 + d] = tanhf(ao[ri]);
    }
}

// K6: seed row = sub   (1 block, 256 thr)
__global__ void k_seed(float* __restrict__ out, long long seed) {
    out[seed * 256 + threadIdx.x] = g_sub[threadIdx.x];
}

// K7: per-edge scatter. 64 threads (16 float4) per edge row.
__global__ void k_edges(const float* __restrict__ entity_table,
                        const int* __restrict__ rel_ids,
                        const int* __restrict__ tail_ids,
                        const int* __restrict__ tails_state,
                        const int* __restrict__ origin_ids,
                        float* __restrict__ out, int E) {
    long long t = (long long)blockIdx.x * blockDim.x + threadIdx.x;
    int e = (int)(t >> 6);
    int j = (int)(t & 63);
    if (e >= E) return;

    int st = tails_state[e];       // warp-uniform (all 32 lanes share e)
    float4 val;
    if (st == 1) {
        long long org = origin_ids[e];
        val = reinterpret_cast<const float4*>(entity_table)[org * 64 + j];
    } else {
        long long r = rel_ids[e];
        val = reinterpret_cast<const float4*>(g_obj)[r * 64 + j];
    }
    long long row = tail_ids[e];
    reinterpret_cast<float4*>(out)[row * 64 + j] = val;
}

extern "C" void kernel_launch(void* const* d_in, const int* in_sizes, int n_in,
                              void* d_out, int out_size) {
    const float* enc        = (const float*)d_in[0];
    const float* mask       = (const float*)d_in[1];
    const float* entity     = (const float*)d_in[2];
    const float* rel_table  = (const float*)d_in[3];
    const float* W_ih       = (const float*)d_in[4];
    const float* W_hh       = (const float*)d_in[5];
    const float* b_ih       = (const float*)d_in[6];
    const float* b_hh       = (const float*)d_in[7];
    const float* sub_W      = (const float*)d_in[8];
    const float* sub_b      = (const float*)d_in[9];
    const float* obj_W      = (const float*)d_in[10];
    const float* obj_b      = (const float*)d_in[11];
    const int*   rel_ids    = (const int*)d_in[12];
    const int*   tail_ids   = (const int*)d_in[13];
    const int*   tails_state= (const int*)d_in[14];
    const int*   origin_ids = (const int*)d_in[15];

    float* out = (float*)d_out;
    int E = in_sizes[12];           // edge count; seed == E by construction
    int R = in_sizes[3] / 256;      // relation vocab

    k_sub<<<1, 256>>>(mask, sub_W, sub_b);
    k_gates_seed<<<3, 256>>>(enc, W_ih, W_hh, b_ih, b_hh);
    k_r0<<<1, 256>>>();
    k_gi2<<<3, 256>>>(W_ih, b_ih);
    k_reltable<<<(R + RT - 1) / RT, 256>>>(rel_table, W_hh, b_hh, obj_W, obj_b, R);
    k_seed<<<1, 256>>>(out, (long long)E);

    long long total = (long long)E * 64;
    int blocks = (int)((total + 255) / 256);
    k_edges<<<blocks, 256>>>(entity, rel_ids, tail_ids, tails_state, origin_ids, out, E);
}

// round 3
// speedup vs baseline: 3.9925x; 3.9925x over previous
#include <cuda_runtime.h>
#include <cuda_bf16.h>

// Scratch (device globals — no allocation allowed)
__device__ float g_sub[256];
__device__ float g_gates_seed[1536]; // [0:768)=gia, [768:1536)=gha
__device__ float g_r0[256];
__device__ float g_gi2[768];
__device__ float g_obj[1024 * 256];  // per-relation output table (R <= 1024)

__device__ __forceinline__ float sigmoidf(float x) {
    return 1.0f / (1.0f + __expf(-x));
}

__device__ __forceinline__ float dot4(float4 a, float4 b) {
    return fmaf(a.x, b.x, fmaf(a.y, b.y, fmaf(a.z, b.z, a.w * b.w)));
}

__device__ __forceinline__ float warp_row_dot(const float* __restrict__ W_row,
                                              const float* __restrict__ x, int lane) {
    const float4* wp = reinterpret_cast<const float4*>(W_row);
    const float4* xp = reinterpret_cast<const float4*>(x);
    float acc = dot4(wp[lane], xp[lane]) + dot4(wp[lane + 32], xp[lane + 32]);
#pragma unroll
    for (int off = 16; off; off >>= 1) acc += __shfl_xor_sync(0xffffffffu, acc, off);
    return acc;
}

// K1: sub = tanh(sample_mask @ sub_W.T + sub_b). 256 warps.
__global__ void k_sub(const float* __restrict__ mask, const float* __restrict__ sub_W,
                      const float* __restrict__ sub_b) {
    int w = (blockIdx.x * blockDim.x + threadIdx.x) >> 5;
    int lane = threadIdx.x & 31;
    if (w >= 256) return;
    float acc = warp_row_dot(sub_W + (size_t)w * 256, mask, lane);
    if (lane == 0) g_sub[w] = tanhf(acc + sub_b[w]);
}

// K2: gia[j] = enc.W_ih[j] + b_ih[j] (j<768); gha[j-768] = sub.W_hh[j-768] + b_hh. 1536 warps.
__global__ void k_gates_seed(const float* __restrict__ enc,
                             const float* __restrict__ W_ih, const float* __restrict__ W_hh,
                             const float* __restrict__ b_ih, const float* __restrict__ b_hh) {
    int w = (blockIdx.x * blockDim.x + threadIdx.x) >> 5;
    int lane = threadIdx.x & 31;
    if (w >= 1536) return;
    float acc, bias;
    if (w < 768) {
        acc = warp_row_dot(W_ih + (size_t)w * 256, enc, lane);
        bias = b_ih[w];
    } else {
        int j = w - 768;
        acc = warp_row_dot(W_hh + (size_t)j * 256, g_sub, lane);
        bias = b_hh[j];
    }
    if (lane == 0) g_gates_seed[w] = acc + bias;
}

// K3: r0 from gates (1 block, 256 thr)
__global__ void k_r0() {
    int d = threadIdx.x;
    const float* gia = g_gates_seed;
    const float* gha = g_gates_seed + 768;
    float r = sigmoidf(gia[d]       + gha[d]);
    float z = sigmoidf(gia[256 + d] + gha[256 + d]);
    float n = tanhf   (gia[512 + d] + r * gha[512 + d]);
    g_r0[d] = (1.0f - z) * n + z * g_sub[d];
}

// K4: gi2[j] = r0 . W_ih[j] + b_ih[j]. 768 warps.
__global__ void k_gi2(const float* __restrict__ W_ih, const float* __restrict__ b_ih) {
    int w = (blockIdx.x * blockDim.x + threadIdx.x) >> 5;
    int lane = threadIdx.x & 31;
    if (w >= 768) return;
    float acc = warp_row_dot(W_ih + (size_t)w * 256, g_r0, lane);
    if (lane == 0) g_gi2[w] = acc + b_ih[w];
}

// K5: per-relation table, RT=8 relations per block, float4 weight loads.
#define RT 8
__global__ void k_reltable(const float* __restrict__ rel_table,
                           const float* __restrict__ W_hh, const float* __restrict__ b_hh,
                           const float* __restrict__ obj_W, const float* __restrict__ obj_b,
                           int R) {
    __shared__ float srel[RT][256];
    int d = threadIdx.x;
    int rbase = blockIdx.x * RT;

#pragma unroll
    for (int ri = 0; ri < RT; ri++) {
        int r = rbase + ri;
        srel[ri][d] = (r < R) ? rel_table[(size_t)r * 256 + d] : 0.0f;
    }
    __syncthreads();

    float ar[RT], az[RT], an[RT];
    {
        float br = b_hh[d], bz = b_hh[256 + d], bn = b_hh[512 + d];
#pragma unroll
        for (int ri = 0; ri < RT; ri++) { ar[ri] = br; az[ri] = bz; an[ri] = bn; }
    }

    const float4* wr4 = reinterpret_cast<const float4*>(W_hh + (size_t)d * 256);
    const float4* wz4 = reinterpret_cast<const float4*>(W_hh + (size_t)(256 + d) * 256);
    const float4* wn4 = reinterpret_cast<const float4*>(W_hh + (size_t)(512 + d) * 256);
#pragma unroll 2
    for (int k4 = 0; k4 < 64; k4++) {
        float4 vr = wr4[k4], vz = wz4[k4], vn = wn4[k4];
#pragma unroll
        for (int ri = 0; ri < RT; ri++) {
            float4 h = *reinterpret_cast<const float4*>(&srel[ri][k4 * 4]); // warp-uniform broadcast
            ar[ri] = fmaf(vr.x, h.x, fmaf(vr.y, h.y, fmaf(vr.z, h.z, fmaf(vr.w, h.w, ar[ri]))));
            az[ri] = fmaf(vz.x, h.x, fmaf(vz.y, h.y, fmaf(vz.z, h.z, fmaf(vz.w, h.w, az[ri]))));
            an[ri] = fmaf(vn.x, h.x, fmaf(vn.y, h.y, fmaf(vn.z, h.z, fmaf(vn.w, h.w, an[ri]))));
        }
    }

    float gr = g_gi2[d], gz = g_gi2[256 + d], gn = g_gi2[512 + d];
    float rj[RT];
#pragma unroll
    for (int ri = 0; ri < RT; ri++) {
        float r = sigmoidf(gr + ar[ri]);
        float z = sigmoidf(gz + az[ri]);
        float n = tanhf(gn + r * an[ri]);
        rj[ri] = (1.0f - z) * n + z * srel[ri][d];
    }
    __syncthreads();
#pragma unroll
    for (int ri = 0; ri < RT; ri++) srel[ri][d] = rj[ri];
    __syncthreads();

    float ao[RT];
    {
        float bo = obj_b[d];
#pragma unroll
        for (int ri = 0; ri < RT; ri++) ao[ri] = bo;
    }
    const float4* wo4 = reinterpret_cast<const float4*>(obj_W + (size_t)d * 256);
#pragma unroll 2
    for (int k4 = 0; k4 < 64; k4++) {
        float4 v = wo4[k4];
#pragma unroll
        for (int ri = 0; ri < RT; ri++) {
            float4 h = *reinterpret_cast<const float4*>(&srel[ri][k4 * 4]);
            ao[ri] = fmaf(v.x, h.x, fmaf(v.y, h.y, fmaf(v.z, h.z, fmaf(v.w, h.w, ao[ri]))));
        }
    }
#pragma unroll
    for (int ri = 0; ri < RT; ri++) {
        int r = rbase + ri;
        if (r < R) g_obj[(size_t)r * 256 + d] = tanhf(ao[ri]);
    }
}

// K6: seed row = sub
__global__ void k_seed(float* __restrict__ out, long long seed) {
    out[seed * 256 + threadIdx.x] = g_sub[threadIdx.x];
}

// K7: per-edge scatter. 64 threads (16 float4) per edge row.
__global__ void k_edges(const float* __restrict__ entity_table,
                        const int* __restrict__ rel_ids,
                        const int* __restrict__ tail_ids,
                        const int* __restrict__ tails_state,
                        const int* __restrict__ origin_ids,
                        float* __restrict__ out, int E) {
    long long t = (long long)blockIdx.x * blockDim.x + threadIdx.x;
    int e = (int)(t >> 6);
    int j = (int)(t & 63);
    if (e >= E) return;

    int st = tails_state[e];       // warp-uniform (all lanes in warp share e pair)
    float4 val;
    if (st == 1) {
        long long org = origin_ids[e];
        val = reinterpret_cast<const float4*>(entity_table)[org * 64 + j];
    } else {
        long long r = rel_ids[e];
        val = reinterpret_cast<const float4*>(g_obj)[r * 64 + j];
    }
    long long row = tail_ids[e];
    reinterpret_cast<float4*>(out)[row * 64 + j] = val;
}

extern "C" void kernel_launch(void* const* d_in, const int* in_sizes, int n_in,
                              void* d_out, int out_size) {
    const float* enc        = (const float*)d_in[0];
    const float* mask       = (const float*)d_in[1];
    const float* entity     = (const float*)d_in[2];
    const float* rel_table  = (const float*)d_in[3];
    const float* W_ih       = (const float*)d_in[4];
    const float* W_hh       = (const float*)d_in[5];
    const float* b_ih       = (const float*)d_in[6];
    const float* b_hh       = (const float*)d_in[7];
    const float* sub_W      = (const float*)d_in[8];
    const float* sub_b      = (const float*)d_in[9];
    const float* obj_W      = (const float*)d_in[10];
    const float* obj_b      = (const float*)d_in[11];
    const int*   rel_ids    = (const int*)d_in[12];
    const int*   tail_ids   = (const int*)d_in[13];
    const int*   tails_state= (const int*)d_in[14];
    const int*   origin_ids = (const int*)d_in[15];

    float* out = (float*)d_out;
    int E = in_sizes[12];           // edge count; seed == E by construction
    int R = in_sizes[3] / 256;      // relation vocab

    // seed chain: warp-per-output GEMVs (512 threads = 16 warps per block)
    k_sub<<<16, 512>>>(mask, sub_W, sub_b);                         // 256 warps
    k_gates_seed<<<96, 512>>>(enc, W_ih, W_hh, b_ih, b_hh);         // 1536 warps
    k_r0<<<1, 256>>>();
    k_gi2<<<48, 512>>>(W_ih, b_ih);                                 // 768 warps
    k_reltable<<<(R + RT - 1) / RT, 256>>>(rel_table, W_hh, b_hh, obj_W, obj_b, R);
    k_seed<<<1, 256>>>(out, (long long)E);

    long long total = (long long)E * 64;
    int blocks = (int)((total + 255) / 256);
    k_edges<<<blocks, 256>>>(entity, rel_ids, tail_ids, tails_state, origin_ids, out, E);
}